// round 12
// baseline (speedup 1.0000x reference)
#include <cuda_runtime.h>
#include <cuda_fp16.h>
#include <cuda_bf16.h>
#include <cstdint>

// Problem constants (fixed by the reference)
#define BB    2048
#define VV    2048
#define CC    512
#define MM    8
#define HH    16
#define EPSF  1e-6f
#define NBLK  148          // persistent: one block per SM
#define PAIRS (BB / 2)     // 1024 row-pairs

// ---- MUFU-free helpers (FMA/ALU pipes only) ----

// Reciprocal: integer-magic seed + 2 Newton steps. q must be positive normal.
__device__ __forceinline__ float recip_nt(float q) {
    float r = __int_as_float(0x7EF311C3 - __float_as_int(q));
    r = r * fmaf(-q, r, 2.0f);
    r = r * fmaf(-q, r, 2.0f);
    return r;
}

// exp2(z) for z in [-28, 0]: magic-add round-to-int, deg-4 poly on the
// fraction, exponent spliced via integer add. No MUFU.
__device__ __forceinline__ float exp2_nomufu(float z) {
    z = fmaxf(z, -28.0f);
    float t = z + 12582912.0f;            // 1.5*2^23: rounds z to nearest int
    float i = t - 12582912.0f;
    float f = z - i;                      // [-0.5, 0.5]
    float p = fmaf(f, 0.009618130f, 0.055504110f);
    p = fmaf(f, p, 0.240226507f);
    p = fmaf(f, p, 0.693147181f);
    p = fmaf(f, p, 1.0f);
    int ib = __float_as_int(t) << 23;     // i * 2^23 (wraps correctly)
    return __int_as_float(__float_as_int(p) + ib);
}

// Eigen-style rational tanh (P13/Q6), division via recip_nt. No MUFU.
__device__ __forceinline__ float tanh_rat(float x) {
    x = fminf(fmaxf(x, -7.90531110763549805f), 7.90531110763549805f);
    float y = x * x;
    float p = fmaf(y, -2.76076847742355e-16f, 2.00018790482477e-13f);
    p = fmaf(y, p, -8.60467152213735e-11f);
    p = fmaf(y, p, 5.12229709037114e-08f);
    p = fmaf(y, p, 1.48572235717979e-05f);
    p = fmaf(y, p, 6.37261928875436e-04f);
    p = fmaf(y, p, 4.89352455891786e-03f);
    float q = fmaf(y, 1.19825839466702e-06f, 1.18534705686654e-04f);
    q = fmaf(y, q, 2.26843463243900e-03f);
    q = fmaf(y, q, 4.89352518554385e-03f);
    return (x * p) * recip_nt(q);         // Q(y) > 0 always
}

// Named *_fast to avoid colliding with cuda_fp16.hpp's h2tanh().
__device__ __forceinline__ __half2 h2tanh_fast(__half2 x) {
    unsigned xi = *reinterpret_cast<unsigned*>(&x), yi;
    asm("tanh.approx.f16x2 %0, %1;" : "=r"(yi) : "r"(xi));
    return *reinterpret_cast<__half2*>(&yi);
}
__device__ __forceinline__ void cpasync16(void* smem_ptr, const float* g) {
    unsigned int saddr = (unsigned int)__cvta_generic_to_shared(smem_ptr);
    asm volatile("cp.async.cg.shared.global [%0], [%1], 16;" :: "r"(saddr), "l"(g));
}
#define CP_COMMIT() asm volatile("cp.async.commit_group;" ::: "memory")
#define CP_WAIT0()  asm volatile("cp.async.wait_group 0;" ::: "memory")

// Persistent kernel: 148 blocks, 512 threads (thread = channel c), 2 rows
// per iteration (f16x2 lanes = rows). The MUFU pipe is the measured binder
// (tanh slots); this version moves the softmax exp/rcp and the h=15 tanh
// column onto the FMA/ALU pipes: 137 -> 120 MUFU slots per thread-row.
__global__ __launch_bounds__(CC, 1) void gradoptim_attn_kernel(
    const float* __restrict__ preds,
    const int*   __restrict__ mask_ids,
    const float* __restrict__ W1,   // (C, 2, H)
    const float* __restrict__ b1,   // (C, H)
    const float* __restrict__ W2,   // (C, H)
    const float* __restrict__ b2,   // (C,)
    float*       __restrict__ out)  // (B, V)
{
    __shared__ float rows[2][2][VV];   // [ring buf][row in pair][col]

    const int c = threadIdx.x;

    // ---- Persistent per-channel weights ----
    // h = 0..14 packed f16x2 (both lanes equal); h = 15 kept in f32 for the
    // rational-tanh path. W1[c,0,:] and b1[c,:] are re-read from L1 each
    // iteration (u depends on the row), so they hold no registers.
    __half2 w1bh[HH - 1], w2h[HH - 1];
    float   w1b15, w2f15;
    {
        const float4* W1p = reinterpret_cast<const float4*>(W1 + (size_t)c * 2 * HH);
        const float4* W2p = reinterpret_cast<const float4*>(W2 + (size_t)c * HH);
        float4 q0 = W1p[4], q1 = W1p[5], q2 = W1p[6], q3 = W1p[7]; // W1[c,1,:]
        float4 s0 = W2p[0], s1 = W2p[1], s2 = W2p[2], s3 = W2p[3]; // W2[c,:]
        w1bh[0]  = __float2half2_rn(q0.x); w1bh[1]  = __float2half2_rn(q0.y);
        w1bh[2]  = __float2half2_rn(q0.z); w1bh[3]  = __float2half2_rn(q0.w);
        w1bh[4]  = __float2half2_rn(q1.x); w1bh[5]  = __float2half2_rn(q1.y);
        w1bh[6]  = __float2half2_rn(q1.z); w1bh[7]  = __float2half2_rn(q1.w);
        w1bh[8]  = __float2half2_rn(q2.x); w1bh[9]  = __float2half2_rn(q2.y);
        w1bh[10] = __float2half2_rn(q2.z); w1bh[11] = __float2half2_rn(q2.w);
        w1bh[12] = __float2half2_rn(q3.x); w1bh[13] = __float2half2_rn(q3.y);
        w1bh[14] = __float2half2_rn(q3.z); w1b15 = q3.w;
        w2h[0]   = __float2half2_rn(s0.x); w2h[1]   = __float2half2_rn(s0.y);
        w2h[2]   = __float2half2_rn(s0.z); w2h[3]   = __float2half2_rn(s0.w);
        w2h[4]   = __float2half2_rn(s1.x); w2h[5]   = __float2half2_rn(s1.y);
        w2h[6]   = __float2half2_rn(s1.z); w2h[7]   = __float2half2_rn(s1.w);
        w2h[8]   = __float2half2_rn(s2.x); w2h[9]   = __float2half2_rn(s2.y);
        w2h[10]  = __float2half2_rn(s2.z); w2h[11]  = __float2half2_rn(s2.w);
        w2h[12]  = __float2half2_rn(s3.x); w2h[13]  = __float2half2_rn(s3.y);
        w2h[14]  = __float2half2_rn(s3.z); w2f15 = s3.w;
    }
    const float b2c = b2[c];

    int idx[MM];
    {
        const int4* mi = reinterpret_cast<const int4*>(mask_ids + (size_t)c * MM);
        int4 i0 = mi[0], i1 = mi[1];
        idx[0] = i0.x; idx[1] = i0.y; idx[2] = i0.z; idx[3] = i0.w;
        idx[4] = i1.x; idx[5] = i1.y; idx[6] = i1.z; idx[7] = i1.w;
    }

    const float LOG2E = 1.4426950408889634f;
    const float4* W1a4 = reinterpret_cast<const float4*>(W1 + (size_t)c * 2 * HH); // W1[c,0,:]
    const float4* b14  = reinterpret_cast<const float4*>(b1 + (size_t)c * HH);

    // ---- Prologue: stage first pair into ring buf 0 ----
    int p = blockIdx.x;
    if (p < PAIRS) {
        cpasync16(&rows[0][0][c * 4], preds + (size_t)(2 * p)     * VV + c * 4);
        cpasync16(&rows[0][1][c * 4], preds + (size_t)(2 * p + 1) * VV + c * 4);
        CP_COMMIT();
    }

    int buf = 0;
    while (p < PAIRS) {
        CP_WAIT0();
        __syncthreads();

        const int pn = p + NBLK;
        if (pn < PAIRS) {
            cpasync16(&rows[buf ^ 1][0][c * 4], preds + (size_t)(2 * pn)     * VV + c * 4);
            cpasync16(&rows[buf ^ 1][1][c * 4], preds + (size_t)(2 * pn + 1) * VV + c * 4);
            CP_COMMIT();
        }

        const int r0 = 2 * p, r1 = 2 * p + 1;

        // Copy untouched tail columns [512,2048) straight from smem.
        if (c >= CC / 4) {
            float4 t0 = reinterpret_cast<float4*>(rows[buf][0])[c];
            float4 t1 = reinterpret_cast<float4*>(rows[buf][1])[c];
            reinterpret_cast<float4*>(out + (size_t)r0 * VV)[c] = t0;
            reinterpret_cast<float4*>(out + (size_t)r1 * VV)[c] = t1;
        }

        const float ha0 = rows[buf][0][c];
        const float ha1 = rows[buf][1][c];

        // u[h] = h_a*W1[c,0,h] + b1[c,h]; packed (r0,r1) for h<15, f32 for h=15.
        // W1a/b1 re-read via L1 each iteration (no persistent registers).
        __half2 uh[HH - 1];
        float u15_0 = 0.0f, u15_1 = 0.0f;
        #pragma unroll
        for (int i = 0; i < 4; i++) {
            float4 a  = W1a4[i];
            float4 bv = b14[i];
            const int h = 4 * i;
            uh[h]     = __floats2half2_rn(fmaf(ha0, a.x, bv.x), fmaf(ha1, a.x, bv.x));
            uh[h + 1] = __floats2half2_rn(fmaf(ha0, a.y, bv.y), fmaf(ha1, a.y, bv.y));
            uh[h + 2] = __floats2half2_rn(fmaf(ha0, a.z, bv.z), fmaf(ha1, a.z, bv.z));
            if (i < 3) {
                uh[h + 3] = __floats2half2_rn(fmaf(ha0, a.w, bv.w), fmaf(ha1, a.w, bv.w));
            } else {
                u15_0 = fmaf(ha0, a.w, bv.w);
                u15_1 = fmaf(ha1, a.w, bv.w);
            }
        }

        // ---- Scores: h=0..14 packed MUFU tanh; h=15 FMA-pipe rational ----
        float sc0[MM], sc1[MM];
        #pragma unroll
        for (int m = 0; m < MM; m++) {
            const float xf0 = rows[buf][0][idx[m]];
            const float xf1 = rows[buf][1][idx[m]];
            __half2 x2 = __floats2half2_rn(xf0, xf1);

            __half2 aE = __float2half2_rn(0.0f);
            __half2 aO = aE;
            #pragma unroll
            for (int i = 0; i < 7; i++) {   // h = 0..13
                const int h = 2 * i;
                aE = __hfma2(w2h[h],     h2tanh_fast(__hfma2(x2, w1bh[h],     uh[h])),     aE);
                aO = __hfma2(w2h[h + 1], h2tanh_fast(__hfma2(x2, w1bh[h + 1], uh[h + 1])), aO);
            }
            aE = __hfma2(w2h[14], h2tanh_fast(__hfma2(x2, w1bh[14], uh[14])), aE);

            // h = 15: rational tanh, zero MUFU.
            float t0 = tanh_rat(fmaf(xf0, w1b15, u15_0));
            float t1 = tanh_rat(fmaf(xf1, w1b15, u15_1));

            float2 fE = __half22float2(aE);
            float2 fO = __half22float2(aO);
            sc0[m] = (fE.x + fO.x) + fmaf(w2f15, t0, b2c);
            sc1[m] = (fE.y + fO.y) + fmaf(w2f15, t1, b2c);
        }

        // ---- Softmax + weighted sum, all off-MUFU ----
        float mx0 = sc0[0], mx1 = sc1[0];
        #pragma unroll
        for (int m = 1; m < MM; m++) {
            mx0 = fmaxf(mx0, sc0[m]);
            mx1 = fmaxf(mx1, sc1[m]);
        }
        float su0 = 0.0f, ws0 = 0.0f, su1 = 0.0f, ws1 = 0.0f;
        #pragma unroll
        for (int m = 0; m < MM; m++) {
            float e0 = exp2_nomufu((sc0[m] - mx0) * LOG2E);
            float e1 = exp2_nomufu((sc1[m] - mx1) * LOG2E);
            su0 += e0;  ws0 = fmaf(e0, rows[buf][0][idx[m]], ws0);
            su1 += e1;  ws1 = fmaf(e1, rows[buf][1][idx[m]], ws1);
        }
        const float cor0 = fmaxf(ha0, ws0 * recip_nt(su0) + EPSF);
        const float cor1 = fmaxf(ha1, ws1 * recip_nt(su1) + EPSF);

        out[(size_t)r0 * VV + c] = cor0;
        out[(size_t)r1 * VV + c] = cor1;

        buf ^= 1;
        p = pn;
    }
}

extern "C" void kernel_launch(void* const* d_in, const int* in_sizes, int n_in,
                              void* d_out, int out_size) {
    (void)in_sizes; (void)n_in; (void)out_size;
    const float* preds    = (const float*)d_in[0];
    // d_in[1] = ground_truth (unused by the reference)
    const int*   mask_ids = (const int*)  d_in[2];
    const float* W1       = (const float*)d_in[3];
    const float* b1       = (const float*)d_in[4];
    const float* W2       = (const float*)d_in[5];
    const float* b2       = (const float*)d_in[6];
    float*       out      = (float*)d_out;

    gradoptim_attn_kernel<<<NBLK, CC>>>(preds, mask_ids, W1, b1, W2, b2, out);
}

// round 13
// speedup vs baseline: 1.1745x; 1.1745x over previous
#include <cuda_runtime.h>
#include <cuda_fp16.h>
#include <cuda_bf16.h>
#include <cstdint>

// Problem constants (fixed by the reference)
#define BB    2048
#define VV    2048
#define CC    512
#define MM    8
#define HH    16
#define EPSF  1e-6f
#define NBLK  148          // persistent: one block per SM
#define PAIRS (BB / 2)     // 1024 row-pairs
#define TPB   1024         // 2 threads per channel (H-split) -> 32 warps/SM

__device__ __forceinline__ float ex2_fast(float x) {
    float y;
    asm("ex2.approx.f32 %0, %1;" : "=f"(y) : "f"(x));
    return y;
}
__device__ __forceinline__ float rcp_fast(float x) {
    float y;
    asm("rcp.approx.f32 %0, %1;" : "=f"(y) : "f"(x));
    return y;
}
// Named *_fast to avoid colliding with cuda_fp16.hpp's h2tanh().
__device__ __forceinline__ __half2 h2tanh_fast(__half2 x) {
    unsigned xi = *reinterpret_cast<unsigned*>(&x), yi;
    asm("tanh.approx.f16x2 %0, %1;" : "=r"(yi) : "r"(xi));
    return *reinterpret_cast<__half2*>(&yi);
}
__device__ __forceinline__ void cpasync16(void* smem_ptr, const float* g) {
    unsigned int saddr = (unsigned int)__cvta_generic_to_shared(smem_ptr);
    asm volatile("cp.async.cg.shared.global [%0], [%1], 16;" :: "r"(saddr), "l"(g));
}
#define CP_COMMIT() asm volatile("cp.async.commit_group;" ::: "memory")
#define CP_WAIT0()  asm volatile("cp.async.wait_group 0;" ::: "memory")

// Latency-exposure fix: 1024 threads/block (32 warps/SM, double R8), two
// threads per channel. Even thread computes h=0..7, odd h=8..15; partial
// scores (both rows packed in f16x2 lanes) are combined with one shfl_xor
// per m. Each thread then softmaxes only its own row (half -> row).
// Memory traffic identical to the 43.2us baseline; per-thread registers
// halved so 32 warps fit the register file.
__global__ __launch_bounds__(TPB, 1) void gradoptim_attn_kernel(
    const float* __restrict__ preds,
    const int*   __restrict__ mask_ids,
    const float* __restrict__ W1,   // (C, 2, H)
    const float* __restrict__ b1,   // (C, H)
    const float* __restrict__ W2,   // (C, H)
    const float* __restrict__ b2,   // (C,)
    float*       __restrict__ out)  // (B, V)
{
    __shared__ float rows[2][2][VV];   // [ring buf][row in pair][col] = 32 KB

    const int t    = threadIdx.x;
    const int c    = t >> 1;           // channel
    const int half = t & 1;            // 0: h=0..7 / row0 epilogue; 1: h=8..15 / row1

    // ---- Own 8 h-values of the per-channel weights ----
    // W1 row = 32 floats (8 float4): [0..3]=W1[c,0,:], [4..7]=W1[c,1,:].
    const float4* W1f4 = reinterpret_cast<const float4*>(W1);
    const float4* b1f4 = reinterpret_cast<const float4*>(b1);
    const float4* W2f4 = reinterpret_cast<const float4*>(W2);
    float4 a0  = W1f4[c * 8 + half * 2 + 0];      // W1[c,0,own 0..3]
    float4 a1  = W1f4[c * 8 + half * 2 + 1];      // W1[c,0,own 4..7]
    float4 q0  = W1f4[c * 8 + 4 + half * 2 + 0];  // W1[c,1,own 0..3]
    float4 q1  = W1f4[c * 8 + 4 + half * 2 + 1];
    float4 bv0 = b1f4[c * 4 + half * 2 + 0];
    float4 bv1 = b1f4[c * 4 + half * 2 + 1];
    float4 s0  = W2f4[c * 4 + half * 2 + 0];
    float4 s1  = W2f4[c * 4 + half * 2 + 1];

    // w1b/w2 broadcast-packed (both lanes equal); w1a/b1 pairs-packed
    // (2 h per reg, unpacked at u-prep) to hold the 64-reg budget.
    __half2 w1bh[8], w2h[8], w1a_pk[4], b1_pk[4];
    w1bh[0] = __float2half2_rn(q0.x); w1bh[1] = __float2half2_rn(q0.y);
    w1bh[2] = __float2half2_rn(q0.z); w1bh[3] = __float2half2_rn(q0.w);
    w1bh[4] = __float2half2_rn(q1.x); w1bh[5] = __float2half2_rn(q1.y);
    w1bh[6] = __float2half2_rn(q1.z); w1bh[7] = __float2half2_rn(q1.w);
    w2h[0] = __float2half2_rn(s0.x);  w2h[1] = __float2half2_rn(s0.y);
    w2h[2] = __float2half2_rn(s0.z);  w2h[3] = __float2half2_rn(s0.w);
    w2h[4] = __float2half2_rn(s1.x);  w2h[5] = __float2half2_rn(s1.y);
    w2h[6] = __float2half2_rn(s1.z);  w2h[7] = __float2half2_rn(s1.w);
    w1a_pk[0] = __floats2half2_rn(a0.x, a0.y);  w1a_pk[1] = __floats2half2_rn(a0.z, a0.w);
    w1a_pk[2] = __floats2half2_rn(a1.x, a1.y);  w1a_pk[3] = __floats2half2_rn(a1.z, a1.w);
    b1_pk[0]  = __floats2half2_rn(bv0.x, bv0.y); b1_pk[1] = __floats2half2_rn(bv0.z, bv0.w);
    b1_pk[2]  = __floats2half2_rn(bv1.x, bv1.y); b1_pk[3] = __floats2half2_rn(bv1.z, bv1.w);

    const float b2c = b2[c];

    int idx[MM];
    {
        const int4* mi = reinterpret_cast<const int4*>(mask_ids + (size_t)c * MM);
        int4 i0 = mi[0], i1 = mi[1];
        idx[0] = i0.x; idx[1] = i0.y; idx[2] = i0.z; idx[3] = i0.w;
        idx[4] = i1.x; idx[5] = i1.y; idx[6] = i1.z; idx[7] = i1.w;
    }

    const float LOG2E = 1.4426950408889634f;
    const int sr = t >> 9;        // staging: which row of the pair (0/1)
    const int sj = t & 511;       // staging: float4 column

    // ---- Prologue: stage first pair into ring buf 0 (1 float4/thread) ----
    int p = blockIdx.x;
    if (p < PAIRS) {
        cpasync16(&rows[0][sr][sj * 4], preds + (size_t)(2 * p + sr) * VV + sj * 4);
        CP_COMMIT();
    }

    int buf = 0;
    while (p < PAIRS) {
        CP_WAIT0();
        __syncthreads();

        const int pn = p + NBLK;
        if (pn < PAIRS) {
            cpasync16(&rows[buf ^ 1][sr][sj * 4],
                      preds + (size_t)(2 * pn + sr) * VV + sj * 4);
            CP_COMMIT();
        }

        // Tail copy [512,2048): 2 rows x 384 float4 = 768, threads t<768.
        if (t < 768) {
            const int rr = (t >= 384) ? 1 : 0;
            const int jj = t - rr * 384;
            float4 v = reinterpret_cast<float4*>(rows[buf][rr])[128 + jj];
            reinterpret_cast<float4*>(out + (size_t)(2 * p + rr) * VV)[128 + jj] = v;
        }

        // ---- u for own 8 h-values; f16x2 lanes = (row0, row1) ----
        const float ha0 = rows[buf][0][c];
        const float ha1 = rows[buf][1][c];
        const __half2 ha2 = __floats2half2_rn(ha0, ha1);
        __half2 uh[8];
        #pragma unroll
        for (int i = 0; i < 4; i++) {
            uh[2*i]   = __hfma2(ha2, __low2half2(w1a_pk[i]),  __low2half2(b1_pk[i]));
            uh[2*i+1] = __hfma2(ha2, __high2half2(w1a_pk[i]), __high2half2(b1_pk[i]));
        }

        // ---- Partial scores (own 8 h), combined with partner via shfl ----
        __half2 sc_h2[MM];    // lanes = rows; full 16-term score after combine
        #pragma unroll
        for (int m = 0; m < MM; m++) {
            __half2 x2 = __floats2half2_rn(rows[buf][0][idx[m]], rows[buf][1][idx[m]]);
            __half2 acc = __float2half2_rn(0.0f);
            #pragma unroll
            for (int h = 0; h < 8; h++)
                acc = __hfma2(w2h[h], h2tanh_fast(__hfma2(x2, w1bh[h], uh[h])), acc);
            unsigned au = *reinterpret_cast<unsigned*>(&acc);
            unsigned pu = __shfl_xor_sync(0xFFFFFFFFu, au, 1);
            sc_h2[m] = __hadd2(acc, *reinterpret_cast<__half2*>(&pu));
        }

        // ---- Epilogue: each thread handles its OWN row (half -> row) ----
        float sc[MM];
        #pragma unroll
        for (int m = 0; m < MM; m++) {
            sc[m] = (half ? __high2float(sc_h2[m]) : __low2float(sc_h2[m])) + b2c;
        }
        float mx = sc[0];
        #pragma unroll
        for (int m = 1; m < MM; m++) mx = fmaxf(mx, sc[m]);

        float sum = 0.0f, ws = 0.0f;
        #pragma unroll
        for (int m = 0; m < MM; m++) {
            float e = ex2_fast((sc[m] - mx) * LOG2E);
            sum += e;
            ws   = fmaf(e, rows[buf][half][idx[m]], ws);
        }
        const float ha_own = half ? ha1 : ha0;
        const float corrected = fmaxf(ha_own, ws * rcp_fast(sum) + EPSF);

        out[(size_t)(2 * p + half) * VV + c] = corrected;

        buf ^= 1;
        p = pn;
    }
}

extern "C" void kernel_launch(void* const* d_in, const int* in_sizes, int n_in,
                              void* d_out, int out_size) {
    (void)in_sizes; (void)n_in; (void)out_size;
    const float* preds    = (const float*)d_in[0];
    // d_in[1] = ground_truth (unused by the reference)
    const int*   mask_ids = (const int*)  d_in[2];
    const float* W1       = (const float*)d_in[3];
    const float* b1       = (const float*)d_in[4];
    const float* W2       = (const float*)d_in[5];
    const float* b2       = (const float*)d_in[6];
    float*       out      = (float*)d_out;

    gradoptim_attn_kernel<<<NBLK, TPB>>>(preds, mask_ids, W1, b1, W2, b2, out);
}

// round 15
// speedup vs baseline: 1.1911x; 1.0141x over previous
#include <cuda_runtime.h>
#include <cuda_fp16.h>
#include <cuda_bf16.h>
#include <cstdint>

// Problem constants (fixed by the reference)
#define BB    2048
#define VV    2048
#define CC    512
#define MM    8
#define HH    16
#define EPSF  1e-6f
#define NBLK  148          // persistent: one block per SM
#define PAIRS (BB / 2)     // 1024 row-pairs
#define TPB   1024         // 2 threads per channel (H-split) -> 32 warps/SM

__device__ __forceinline__ float rcp_fast(float x) {
    float y;
    asm("rcp.approx.f32 %0, %1;" : "=f"(y) : "f"(x));
    return y;
}
// Named *_fast to avoid colliding with cuda_fp16.hpp's h2tanh().
__device__ __forceinline__ __half2 h2tanh_fast(__half2 x) {
    unsigned xi = *reinterpret_cast<unsigned*>(&x), yi;
    asm("tanh.approx.f16x2 %0, %1;" : "=r"(yi) : "r"(xi));
    return *reinterpret_cast<__half2*>(&yi);
}
// Reciprocal: integer-magic seed + 2 Newton steps (FMA/ALU pipes only).
__device__ __forceinline__ float recip_nt(float q) {
    float r = __int_as_float(0x7EF311C3 - __float_as_int(q));
    r = r * fmaf(-q, r, 2.0f);
    r = r * fmaf(-q, r, 2.0f);
    return r;
}
// exp2(z), z in [-28, 0]: magic-add round, deg-4 poly, exponent splice. No MUFU.
__device__ __forceinline__ float exp2_nomufu(float z) {
    z = fmaxf(z, -28.0f);
    float t = z + 12582912.0f;
    float i = t - 12582912.0f;
    float f = z - i;
    float p = fmaf(f, 0.009618130f, 0.055504110f);
    p = fmaf(f, p, 0.240226507f);
    p = fmaf(f, p, 0.693147181f);
    p = fmaf(f, p, 1.0f);
    int ib = __float_as_int(t) << 23;
    return __int_as_float(__float_as_int(p) + ib);
}
// Eigen-style rational tanh (P13/Q6), division via recip_nt. No MUFU.
__device__ __forceinline__ float tanh_rat(float x) {
    x = fminf(fmaxf(x, -7.90531110763549805f), 7.90531110763549805f);
    float y = x * x;
    float p = fmaf(y, -2.76076847742355e-16f, 2.00018790482477e-13f);
    p = fmaf(y, p, -8.60467152213735e-11f);
    p = fmaf(y, p, 5.12229709037114e-08f);
    p = fmaf(y, p, 1.48572235717979e-05f);
    p = fmaf(y, p, 6.37261928875436e-04f);
    p = fmaf(y, p, 4.89352455891786e-03f);
    float q = fmaf(y, 1.19825839466702e-06f, 1.18534705686654e-04f);
    q = fmaf(y, q, 2.26843463243900e-03f);
    q = fmaf(y, q, 4.89352518554385e-03f);
    return (x * p) * recip_nt(q);
}
__device__ __forceinline__ void cpasync16(void* smem_ptr, const float* g) {
    unsigned int saddr = (unsigned int)__cvta_generic_to_shared(smem_ptr);
    asm volatile("cp.async.cg.shared.global [%0], [%1], 16;" :: "r"(saddr), "l"(g));
}
#define CP_COMMIT() asm volatile("cp.async.commit_group;" ::: "memory")
#define CP_WAIT0()  asm volatile("cp.async.wait_group 0;" ::: "memory")

// MUFU-offload on the H-split base: 1024 threads (2 per channel; even thread
// h=0..7, odd h=8..15), 2 rows per iteration in f16x2 lanes. MUFU packed tanh
// is the measured binder (rt16 model fits all prior rounds); this version
// moves 1 of each thread's 8 tanh columns to the FMA-pipe rational tanh and
// the softmax exp to a bit-trick exp2 — balancing MUFU (~7.2K cyc) against
// FMA (~7.2K cyc) per SMSP-pair vs the old 8.8K MUFU wall.
__global__ __launch_bounds__(TPB, 1) void gradoptim_attn_kernel(
    const float* __restrict__ preds,
    const int*   __restrict__ mask_ids,
    const float* __restrict__ W1,   // (C, 2, H)
    const float* __restrict__ b1,   // (C, H)
    const float* __restrict__ W2,   // (C, H)
    const float* __restrict__ b2,   // (C,)
    float*       __restrict__ out)  // (B, V)
{
    __shared__ float rows[2][2][VV];   // [ring buf][row in pair][col] = 32 KB

    const int t    = threadIdx.x;
    const int c    = t >> 1;           // channel
    const int half = t & 1;            // 0: h=0..7 / row0 epilogue; 1: h=8..15 / row1

    // ---- Own 8 h-values of the per-channel weights ----
    const float4* W1f4 = reinterpret_cast<const float4*>(W1);
    const float4* b1f4 = reinterpret_cast<const float4*>(b1);
    const float4* W2f4 = reinterpret_cast<const float4*>(W2);
    float4 a0  = W1f4[c * 8 + half * 2 + 0];      // W1[c,0,own 0..3]
    float4 a1  = W1f4[c * 8 + half * 2 + 1];      // W1[c,0,own 4..7]
    float4 q0  = W1f4[c * 8 + 4 + half * 2 + 0];  // W1[c,1,own 0..3]
    float4 q1  = W1f4[c * 8 + 4 + half * 2 + 1];
    float4 bv0 = b1f4[c * 4 + half * 2 + 0];
    float4 bv1 = b1f4[c * 4 + half * 2 + 1];
    float4 s0  = W2f4[c * 4 + half * 2 + 0];
    float4 s1  = W2f4[c * 4 + half * 2 + 1];

    // h_local 0..6: packed MUFU path. h_local 7: f32 FMA-pipe rational path.
    __half2 w1bh[7], w2h[7], w1a_pk[4], b1_pk[4];
    w1bh[0] = __float2half2_rn(q0.x); w1bh[1] = __float2half2_rn(q0.y);
    w1bh[2] = __float2half2_rn(q0.z); w1bh[3] = __float2half2_rn(q0.w);
    w1bh[4] = __float2half2_rn(q1.x); w1bh[5] = __float2half2_rn(q1.y);
    w1bh[6] = __float2half2_rn(q1.z);
    w2h[0] = __float2half2_rn(s0.x);  w2h[1] = __float2half2_rn(s0.y);
    w2h[2] = __float2half2_rn(s0.z);  w2h[3] = __float2half2_rn(s0.w);
    w2h[4] = __float2half2_rn(s1.x);  w2h[5] = __float2half2_rn(s1.y);
    w2h[6] = __float2half2_rn(s1.z);
    w1a_pk[0] = __floats2half2_rn(a0.x, a0.y);  w1a_pk[1] = __floats2half2_rn(a0.z, a0.w);
    w1a_pk[2] = __floats2half2_rn(a1.x, a1.y);  w1a_pk[3] = __float2half2_rn(a1.z);
    b1_pk[0]  = __floats2half2_rn(bv0.x, bv0.y); b1_pk[1] = __floats2half2_rn(bv0.z, bv0.w);
    b1_pk[2]  = __floats2half2_rn(bv1.x, bv1.y); b1_pk[3] = __float2half2_rn(bv1.z);
    const float   w1b7 = q1.w;              // W1[c,1,own7]
    const __half2 w2h7 = __float2half2_rn(s1.w);
    const float   w1a7 = a1.w, b17 = bv1.w;

    const float b2c = b2[c];

    int idx[MM];
    {
        const int4* mi = reinterpret_cast<const int4*>(mask_ids + (size_t)c * MM);
        int4 i0 = mi[0], i1 = mi[1];
        idx[0] = i0.x; idx[1] = i0.y; idx[2] = i0.z; idx[3] = i0.w;
        idx[4] = i1.x; idx[5] = i1.y; idx[6] = i1.z; idx[7] = i1.w;
    }

    const float LOG2E = 1.4426950408889634f;
    const int sr = t >> 9;        // staging: which row of the pair (0/1)
    const int sj = t & 511;       // staging: float4 column

    // ---- Prologue: stage first pair into ring buf 0 (1 float4/thread) ----
    int p = blockIdx.x;
    if (p < PAIRS) {
        cpasync16(&rows[0][sr][sj * 4], preds + (size_t)(2 * p + sr) * VV + sj * 4);
        CP_COMMIT();
    }

    int buf = 0;
    while (p < PAIRS) {
        CP_WAIT0();
        __syncthreads();

        const int pn = p + NBLK;
        if (pn < PAIRS) {
            cpasync16(&rows[buf ^ 1][sr][sj * 4],
                      preds + (size_t)(2 * pn + sr) * VV + sj * 4);
            CP_COMMIT();
        }

        // Tail copy [512,2048): 2 rows x 384 float4 = 768, threads t<768.
        if (t < 768) {
            const int rr = (t >= 384) ? 1 : 0;
            const int jj = t - rr * 384;
            float4 v = reinterpret_cast<float4*>(rows[buf][rr])[128 + jj];
            reinterpret_cast<float4*>(out + (size_t)(2 * p + rr) * VV)[128 + jj] = v;
        }

        // ---- u for own h-values; f16x2 lanes = (row0, row1) ----
        const float ha0 = rows[buf][0][c];
        const float ha1 = rows[buf][1][c];
        const __half2 ha2 = __floats2half2_rn(ha0, ha1);
        __half2 uh[7];
        #pragma unroll
        for (int i = 0; i < 3; i++) {
            uh[2*i]   = __hfma2(ha2, __low2half2(w1a_pk[i]),  __low2half2(b1_pk[i]));
            uh[2*i+1] = __hfma2(ha2, __high2half2(w1a_pk[i]), __high2half2(b1_pk[i]));
        }
        uh[6] = __hfma2(ha2, w1a_pk[3], b1_pk[3]);
        const float u7_0 = fmaf(ha0, w1a7, b17);
        const float u7_1 = fmaf(ha1, w1a7, b17);

        // ---- Partial scores: 7 packed MUFU tanh + 1 FMA-pipe rational ----
        __half2 sc_h2[MM];
        #pragma unroll
        for (int m = 0; m < MM; m++) {
            const float xf0 = rows[buf][0][idx[m]];
            const float xf1 = rows[buf][1][idx[m]];
            __half2 x2 = __floats2half2_rn(xf0, xf1);
            __half2 acc = __float2half2_rn(0.0f);
            #pragma unroll
            for (int h = 0; h < 7; h++)
                acc = __hfma2(w2h[h], h2tanh_fast(__hfma2(x2, w1bh[h], uh[h])), acc);
            // h_local 7: rational tanh on the FMA pipe (both rows, f32).
            float t0 = tanh_rat(fmaf(xf0, w1b7, u7_0));
            float t1 = tanh_rat(fmaf(xf1, w1b7, u7_1));
            acc = __hfma2(w2h7, __floats2half2_rn(t0, t1), acc);

            unsigned au = *reinterpret_cast<unsigned*>(&acc);
            unsigned pu = __shfl_xor_sync(0xFFFFFFFFu, au, 1);
            sc_h2[m] = __hadd2(acc, *reinterpret_cast<__half2*>(&pu));
        }

        // ---- Epilogue: each thread handles its OWN row (half -> row) ----
        float sc[MM];
        #pragma unroll
        for (int m = 0; m < MM; m++)
            sc[m] = (half ? __high2float(sc_h2[m]) : __low2float(sc_h2[m])) + b2c;

        float mx = sc[0];
        #pragma unroll
        for (int m = 1; m < MM; m++) mx = fmaxf(mx, sc[m]);

        float sum = 0.0f, ws = 0.0f;
        #pragma unroll
        for (int m = 0; m < MM; m++) {
            float e = exp2_nomufu((sc[m] - mx) * LOG2E);   // FMA pipe, not MUFU
            sum += e;
            ws   = fmaf(e, rows[buf][half][idx[m]], ws);
        }
        const float ha_own = half ? ha1 : ha0;
        const float corrected = fmaxf(ha_own, ws * rcp_fast(sum) + EPSF);

        out[(size_t)(2 * p + half) * VV + c] = corrected;

        buf ^= 1;
        p = pn;
    }
}

extern "C" void kernel_launch(void* const* d_in, const int* in_sizes, int n_in,
                              void* d_out, int out_size) {
    (void)in_sizes; (void)n_in; (void)out_size;
    const float* preds    = (const float*)d_in[0];
    // d_in[1] = ground_truth (unused by the reference)
    const int*   mask_ids = (const int*)  d_in[2];
    const float* W1       = (const float*)d_in[3];
    const float* b1       = (const float*)d_in[4];
    const float* W2       = (const float*)d_in[5];
    const float* b2       = (const float*)d_in[6];
    float*       out      = (float*)d_out;

    gradoptim_attn_kernel<<<NBLK, TPB>>>(preds, mask_ids, W1, b1, W2, b2, out);
}